// round 15
// baseline (speedup 1.0000x reference)
#include <cuda_runtime.h>
#include <cuda_fp16.h>
#include <cstdint>

#define BB 2
#define DD 64
#define MAXN 50000
#define MAXE 800000
#define SCAN_B 1024
#define TRANS_BLOCKS 296

// ---------------- static device scratch (no allocations allowed) -----------
__device__ uint2 g_Ph[(size_t)MAXN * 32];      // fp16 P, [node][batch][64] = 256B/node
__device__ int   g_deg[MAXN];                  // zeroed by k_scan after reading
__device__ int   g_off[MAXN + 1];              // block-local exclusive prefix
__device__ int   g_bsum[64];                   // per-scan-block base (exclusive)
__device__ int   g_ctr;                        // decoupled-scan block counter
__device__ uint2 g_rank[MAXE];                 // (rank_u, rank_v) per edge
__device__ uint2 g_adj[2 * MAXE];              // (nbr, gate-bits)

// ---------------- PDL intrinsics (sm_90+) -----------------------------------
__device__ __forceinline__ void gdc_wait() {
    asm volatile("griddepcontrol.wait;" ::: "memory");
}
__device__ __forceinline__ void gdc_launch_dependents() {
    asm volatile("griddepcontrol.launch_dependents;");
}

// ---------------- small helpers ---------------------------------------------
__device__ __forceinline__ unsigned long long pack2(float lo, float hi) {
    unsigned long long r;
    asm("mov.b64 %0, {%1, %2};" : "=l"(r) : "f"(lo), "f"(hi));
    return r;
}
__device__ __forceinline__ float2 unpack2(unsigned long long v) {
    float2 r;
    asm("mov.b64 {%0, %1}, %2;" : "=f"(r.x), "=f"(r.y) : "l"(v));
    return r;
}
__device__ __forceinline__ void ffma2(unsigned long long& d,
                                      unsigned long long a,
                                      unsigned long long b) {
    asm("fma.rn.f32x2 %0, %1, %2, %0;" : "+l"(d) : "l"(a), "l"(b));
}
__device__ __forceinline__ unsigned pack_h2(float a, float b) {
    __half2 h = __floats2half2_rn(a, b);
    return *reinterpret_cast<unsigned*>(&h);
}
__device__ __forceinline__ float2 unpack_h2(unsigned u) {
    __half2 h = *reinterpret_cast<__half2*>(&u);
    return __half22float2(h);
}

// ---------------------------------------------------------------------------
// Transform: P = prev @ W^T, persistent grid, PDL primary (fires at t~0).
// ---------------------------------------------------------------------------
__global__ __launch_bounds__(256)
void k_transform(const float* __restrict__ prev, const float* __restrict__ W,
                 int nRows, int N)
{
    gdc_launch_dependents();

    __shared__ float As[64][66];
    __shared__ float Wt[64][64];

    int tid = threadIdx.x;

#pragma unroll
    for (int j = 0; j < 4; j++) {
        int f4 = tid + j * 256;
        int e = f4 >> 4, k4 = f4 & 15;
        float4 w = reinterpret_cast<const float4*>(W)[f4];
        Wt[k4 * 4 + 0][e] = w.x;
        Wt[k4 * 4 + 1][e] = w.y;
        Wt[k4 * 4 + 2][e] = w.z;
        Wt[k4 * 4 + 3][e] = w.w;
    }

    int nTiles = (nRows + 63) >> 6;
    int colg = tid & 15;
    int rowg = tid >> 4;

    for (int tile = blockIdx.x; tile < nTiles; tile += gridDim.x) {
        int row0 = tile * 64;
        __syncthreads();

#pragma unroll
        for (int j = 0; j < 4; j++) {
            int f4 = tid + j * 256;
            int r = f4 >> 4, c4 = f4 & 15;
            float4 a = make_float4(0.f, 0.f, 0.f, 0.f);
            if (row0 + r < nRows)
                a = reinterpret_cast<const float4*>(prev)[(size_t)(row0 + r) * 16 + c4];
            As[c4 * 4 + 0][r] = a.x;
            As[c4 * 4 + 1][r] = a.y;
            As[c4 * 4 + 2][r] = a.z;
            As[c4 * 4 + 3][r] = a.w;
        }
        __syncthreads();

        unsigned long long acc[2][4] = {};

#pragma unroll 8
        for (int k = 0; k < 64; k++) {
            const unsigned long long* ar =
                reinterpret_cast<const unsigned long long*>(&As[k][rowg * 4]);
            unsigned long long A0 = ar[0];
            unsigned long long A1 = ar[1];
            float4 w = *reinterpret_cast<const float4*>(&Wt[k][colg * 4]);
            unsigned long long w0 = pack2(w.x, w.x);
            unsigned long long w1 = pack2(w.y, w.y);
            unsigned long long w2 = pack2(w.z, w.z);
            unsigned long long w3 = pack2(w.w, w.w);
            ffma2(acc[0][0], A0, w0); ffma2(acc[0][1], A0, w1);
            ffma2(acc[0][2], A0, w2); ffma2(acc[0][3], A0, w3);
            ffma2(acc[1][0], A1, w0); ffma2(acc[1][1], A1, w1);
            ffma2(acc[1][2], A1, w2); ffma2(acc[1][3], A1, w3);
        }

#pragma unroll
        for (int p = 0; p < 2; p++) {
            float2 v0 = unpack2(acc[p][0]);
            float2 v1 = unpack2(acc[p][1]);
            float2 v2 = unpack2(acc[p][2]);
            float2 v3 = unpack2(acc[p][3]);
            int rA = row0 + rowg * 4 + p * 2;
            int rB = rA + 1;
            if (rA < nRows) {
                int b = (rA >= N) ? 1 : 0;
                int n = rA - b * N;
                g_Ph[(size_t)n * 32 + b * 16 + colg] =
                    make_uint2(pack_h2(v0.x, v1.x), pack_h2(v2.x, v3.x));
            }
            if (rB < nRows) {
                int b = (rB >= N) ? 1 : 0;
                int n = rB - b * N;
                g_Ph[(size_t)n * 32 + b * 16 + colg] =
                    make_uint2(pack_h2(v0.y, v1.y), pack_h2(v2.y, v3.y));
            }
        }
    }
}

// ---------------------------------------------------------------------------
// Count + rank (PDL secondary of transform, independent -> no wait).
// g_deg arrives zeroed (initial load state; k_scan re-zeroes every call).
// ---------------------------------------------------------------------------
__global__ __launch_bounds__(256)
void k_count_rank(const int* __restrict__ edges, int E)
{
    gdc_launch_dependents();
    int i = blockIdx.x * blockDim.x + threadIdx.x;
    int Eh = E >> 1;
    if (i < Eh) {
        int4 e2 = reinterpret_cast<const int4*>(edges)[i];
        unsigned r0 = atomicAdd(&g_deg[e2.x], 1);
        unsigned r1 = atomicAdd(&g_deg[e2.y], 1);
        unsigned r2 = atomicAdd(&g_deg[e2.z], 1);
        unsigned r3 = atomicAdd(&g_deg[e2.w], 1);
        reinterpret_cast<uint4*>(g_rank)[i] = make_uint4(r0, r1, r2, r3);
    } else if (i == Eh && (E & 1)) {
        int e = E - 1;
        int u = edges[2 * (size_t)e];
        int v = edges[2 * (size_t)e + 1];
        unsigned ru = atomicAdd(&g_deg[u], 1);
        unsigned rv = atomicAdd(&g_deg[v], 1);
        g_rank[e] = make_uint2(ru, rv);
    }
}

// ---------------------------------------------------------------------------
// Single-launch scan: warp-shuffle block scan + decoupled last-block finish.
// Zeroes g_deg after reading (replaces the memset launch). Writes:
//   g_off[i]  = block-local exclusive prefix (i in [0,N]), g_off[N] incl. tail
//   g_bsum[t] = exclusive base for scan block t (all 64 slots valid)
// ---------------------------------------------------------------------------
__global__ __launch_bounds__(SCAN_B)
void k_scan(int N, int nBlocks)
{
    gdc_launch_dependents();
    gdc_wait();

    __shared__ int wsum[32];
    __shared__ int sh64[64];
    __shared__ int s_amLast;

    int t = threadIdx.x, lane = t & 31, w = t >> 5;
    int i = blockIdx.x * SCAN_B + t;

    int d = (i < N) ? g_deg[i] : 0;
    if (i < N) g_deg[i] = 0;                    // coalesced self-clean

    int x = d;
#pragma unroll
    for (int s = 1; s < 32; s <<= 1) {
        int y = __shfl_up_sync(0xffffffffu, x, s);
        if (lane >= s) x += y;
    }
    if (lane == 31) wsum[w] = x;
    __syncthreads();
    if (w == 0) {
        int ws = wsum[lane];
#pragma unroll
        for (int s = 1; s < 32; s <<= 1) {
            int y = __shfl_up_sync(0xffffffffu, ws, s);
            if (lane >= s) ws += y;
        }
        wsum[lane] = ws;
    }
    __syncthreads();

    int base = (w > 0) ? wsum[w - 1] : 0;
    int excl = base + x - d;
    if (i < N) g_off[i] = excl;
    if (i == N - 1) g_off[N] = excl + d;        // local inclusive tail
    if (t == SCAN_B - 1) g_bsum[blockIdx.x] = wsum[31];

    // decoupled last-block finish: scan the block sums
    __threadfence();
    if (t == 0) {
        int prev = atomicAdd(&g_ctr, 1);
        s_amLast = (prev == nBlocks - 1);
    }
    __syncthreads();
    if (!s_amLast) return;                      // block-uniform -> safe

    int v = 0;
    if (t < 64) {
        v = (t < nBlocks) ? g_bsum[t] : 0;
        sh64[t] = v;
    }
    __syncthreads();
    for (int s = 1; s < 64; s <<= 1) {
        int o = (t >= s && t < 64) ? sh64[t - s] : 0;
        __syncthreads();
        if (t < 64) sh64[t] += o;
        __syncthreads();
    }
    if (t < 64) g_bsum[t] = sh64[t] - v;        // exclusive base, all 64 slots
    if (t == 0) g_ctr = 0;                      // reset for next call
}

// ---------------------------------------------------------------------------
// Atomic-free fill (PDL secondary of k_scan).
// ---------------------------------------------------------------------------
__global__ __launch_bounds__(256)
void k_fill(const int* __restrict__ edges, const float* __restrict__ status,
            int E)
{
    gdc_wait();
    int i = blockIdx.x * blockDim.x + threadIdx.x;
    int Eh = E >> 1;
    if (i < Eh) {
        int4  e2 = reinterpret_cast<const int4*>(edges)[i];
        uint4 r2 = reinterpret_cast<const uint4*>(g_rank)[i];
        float2 st = reinterpret_cast<const float2*>(status)[i];
        unsigned g0 = __float_as_uint(st.x);
        unsigned g1 = __float_as_uint(st.y);
        int o0 = g_off[e2.x] + g_bsum[e2.x >> 10] + (int)r2.x;
        int o1 = g_off[e2.y] + g_bsum[e2.y >> 10] + (int)r2.y;
        int o2 = g_off[e2.z] + g_bsum[e2.z >> 10] + (int)r2.z;
        int o3 = g_off[e2.w] + g_bsum[e2.w >> 10] + (int)r2.w;
        g_adj[o0] = make_uint2((unsigned)e2.y, g0);
        g_adj[o1] = make_uint2((unsigned)e2.x, g0);
        g_adj[o2] = make_uint2((unsigned)e2.w, g1);
        g_adj[o3] = make_uint2((unsigned)e2.z, g1);
    } else if (i == Eh && (E & 1)) {
        int e = E - 1;
        int u = edges[2 * (size_t)e];
        int v = edges[2 * (size_t)e + 1];
        uint2 r = g_rank[e];
        unsigned gb = __float_as_uint(status[e]);
        g_adj[g_off[u] + g_bsum[u >> 10] + (int)r.x] = make_uint2((unsigned)v, gb);
        g_adj[g_off[v] + g_bsum[v >> 10] + (int)r.y] = make_uint2((unsigned)u, gb);
    }
}

// ---------------------------------------------------------------------------
// Gather + epilogue (paired-edge LDG.128 layout, unchanged from R14 except
// `end` now comes from g_off[node+1] since g_deg is zeroed by k_scan).
// ---------------------------------------------------------------------------
__global__ __launch_bounds__(128)
void k_gather_final(const float* __restrict__ nodef,
                    const float* __restrict__ edgef,
                    float* __restrict__ out, int N)
{
    int node = (blockIdx.x * blockDim.x + threadIdx.x) >> 5;
    if (node >= N) return;
    int lane = threadIdx.x & 31;
    int half = lane >> 4;
    int sl   = lane & 15;

    int beg = __ldg(&g_off[node])     + __ldg(&g_bsum[node >> 10]);
    int end = __ldg(&g_off[node + 1]) + __ldg(&g_bsum[(node + 1) >> 10]);

    const uint4* P4 = reinterpret_cast<const uint4*>(g_Ph);  // 16 uint4 / node

    float4 accA = make_float4(0.f, 0.f, 0.f, 0.f);
    float4 accB = make_float4(0.f, 0.f, 0.f, 0.f);

    int e = beg;
    for (; e + 15 < end; e += 16) {
        uint2 a0 = g_adj[e +  0 + half];
        uint2 a1 = g_adj[e +  2 + half];
        uint2 a2 = g_adj[e +  4 + half];
        uint2 a3 = g_adj[e +  6 + half];
        uint2 a4 = g_adj[e +  8 + half];
        uint2 a5 = g_adj[e + 10 + half];
        uint2 a6 = g_adj[e + 12 + half];
        uint2 a7 = g_adj[e + 14 + half];
        uint4 q0 = __ldg(P4 + (size_t)a0.x * 16 + sl);
        uint4 q1 = __ldg(P4 + (size_t)a1.x * 16 + sl);
        uint4 q2 = __ldg(P4 + (size_t)a2.x * 16 + sl);
        uint4 q3 = __ldg(P4 + (size_t)a3.x * 16 + sl);
        uint4 q4 = __ldg(P4 + (size_t)a4.x * 16 + sl);
        uint4 q5 = __ldg(P4 + (size_t)a5.x * 16 + sl);
        uint4 q6 = __ldg(P4 + (size_t)a6.x * 16 + sl);
        uint4 q7 = __ldg(P4 + (size_t)a7.x * 16 + sl);
#define ACC_Q(q, gbits)                                                   \
        {                                                                 \
            float g = __uint_as_float(gbits);                             \
            float2 f0 = unpack_h2((q).x), f1 = unpack_h2((q).y);          \
            float2 f2 = unpack_h2((q).z), f3 = unpack_h2((q).w);          \
            accA.x += f0.x * g; accA.y += f0.y * g;                       \
            accA.z += f1.x * g; accA.w += f1.y * g;                       \
            accB.x += f2.x * g; accB.y += f2.y * g;                       \
            accB.z += f3.x * g; accB.w += f3.y * g;                       \
        }
        ACC_Q(q0, a0.y) ACC_Q(q1, a1.y) ACC_Q(q2, a2.y) ACC_Q(q3, a3.y)
        ACC_Q(q4, a4.y) ACC_Q(q5, a5.y) ACC_Q(q6, a6.y) ACC_Q(q7, a7.y)
    }
    if (e < end) {
#pragma unroll
        for (int p = 0; p < 8; p++) {
            int idx = e + p * 2 + half;
            int cl  = (idx < end) ? idx : beg;
            uint2 a = g_adj[cl];
            uint4 q = __ldg(P4 + (size_t)a.x * 16 + sl);
            unsigned gb = (idx < end) ? a.y : 0u;
            ACC_Q(q, gb)
        }
    }
#undef ACC_Q

    accA.x += __shfl_xor_sync(0xffffffffu, accA.x, 16);
    accA.y += __shfl_xor_sync(0xffffffffu, accA.y, 16);
    accA.z += __shfl_xor_sync(0xffffffffu, accA.z, 16);
    accA.w += __shfl_xor_sync(0xffffffffu, accA.w, 16);
    accB.x += __shfl_xor_sync(0xffffffffu, accB.x, 16);
    accB.y += __shfl_xor_sync(0xffffffffu, accB.y, 16);
    accB.z += __shfl_xor_sync(0xffffffffu, accB.z, 16);
    accB.w += __shfl_xor_sync(0xffffffffu, accB.w, 16);

    int b  = sl >> 3;
    int d8 = sl & 7;
    size_t o = ((size_t)b * N + node) * 16 + d8 * 2 + half;
    float4 nf = reinterpret_cast<const float4*>(nodef)[o];
    float4 ef = reinterpret_cast<const float4*>(edgef)[o];
    float4 r = (half == 0) ? accA : accB;

    float4 s;
    s.x = nf.x + ef.x + r.x;
    s.y = nf.y + ef.y + r.y;
    s.z = nf.z + ef.z + r.z;
    s.w = nf.w + ef.w + r.w;
    s.x = (s.x >= 0.f) ? s.x : 0.01f * s.x;
    s.y = (s.y >= 0.f) ? s.y : 0.01f * s.y;
    s.z = (s.z >= 0.f) ? s.z : 0.01f * s.z;
    s.w = (s.w >= 0.f) ? s.w : 0.01f * s.w;

    reinterpret_cast<float4*>(out)[o] = s;
}

// ---------------------------------------------------------------------------
template <typename K, typename... Args>
static inline void launch_pdl(K kernel, dim3 grid, dim3 block, Args... args)
{
    cudaLaunchConfig_t cfg = {};
    cfg.gridDim = grid;
    cfg.blockDim = block;
    cfg.dynamicSmemBytes = 0;
    cfg.stream = 0;
    cudaLaunchAttribute attr[1];
    attr[0].id = cudaLaunchAttributeProgrammaticStreamSerialization;
    attr[0].val.programmaticStreamSerializationAllowed = 1;
    cfg.attrs = attr;
    cfg.numAttrs = 1;
    cudaLaunchKernelEx(&cfg, kernel, args...);
}

extern "C" void kernel_launch(void* const* d_in, const int* in_sizes, int n_in,
                              void* d_out, int out_size)
{
    const float* prev  = (const float*)d_in[0];
    const int*   edges = (const int*)  d_in[1];
    const float* nodef = (const float*)d_in[2];
    const float* edgef = (const float*)d_in[3];
    const float* stat  = (const float*)d_in[4];
    const float* W     = (const float*)d_in[5];
    float* out = (float*)d_out;

    int E     = in_sizes[4];
    int nRows = in_sizes[0] / DD;   // B*N
    int N     = nRows / BB;

    int Epair  = (E >> 1) + 1;
    int nScanB = (N + SCAN_B - 1) / SCAN_B;

    k_transform<<<TRANS_BLOCKS, 256>>>(prev, W, nRows, N);

    launch_pdl(k_count_rank, dim3((Epair + 255) / 256), dim3(256), edges, E);
    launch_pdl(k_scan,       dim3(nScanB), dim3(SCAN_B), N, nScanB);
    launch_pdl(k_fill,       dim3((Epair + 255) / 256), dim3(256), edges, stat, E);

    long long th = (long long)N * 32;
    k_gather_final<<<(unsigned)((th + 127) / 128), 128>>>(nodef, edgef, out, N);
}